// round 11
// baseline (speedup 1.0000x reference)
#include <cuda_runtime.h>

#define BATCH    512
#define TLEN     2048
#define CH       34      // true channel count (2*17)
#define P        36      // padded homogeneous dim
#define PP       37      // kernel_b / gram-S row pitch
#define GPITCH   44      // gram Hs pitch (floats): 16B-aligned rows, spread banks
#define TT       128     // t-tile for Gram phase
#define NTHREADS 256     // gram threads
#define NTB      512     // kernel_b threads
#define NGBLK    25      // upper 8x4 blocks over 40x36
#define NPH      10      // t-phases per gram block
#define NSPLIT   4
#define TSPLIT   (TLEN / NSPLIT)
#define CTT3     128     // kernel_c t-tile (= threads, 1 t per thread)

typedef unsigned long long ull;

// Per-batch fused head matrix: W1f[b][16][35] (homogeneous: col 34 = bias)
__device__ float g_W1f[BATCH * 16 * 35];
// Partial Gram matrices: g_part[b][s][36][36]
__device__ float g_part[BATCH * NSPLIT * P * P];

// ---------------- packed f32x2 helpers (sm_103a FFMA2) ----------------------

__device__ __forceinline__ ull pack2(float lo, float hi) {
    ull r; asm("mov.b64 %0, {%1, %2};" : "=l"(r) : "f"(lo), "f"(hi)); return r;
}
__device__ __forceinline__ void unpack2(ull v, float& lo, float& hi) {
    asm("mov.b64 {%0, %1}, %2;" : "=f"(lo), "=f"(hi) : "l"(v));
}
__device__ __forceinline__ void fma2(ull& d, ull a, ull b) {
    asm("fma.rn.f32x2 %0, %1, %2, %0;" : "+l"(d) : "l"(a), "l"(b));
}

// ---------------- 36x36 shared-memory matmuls (432 active threads) ----------

__device__ __forceinline__ void mm_nn(float (*D)[PP], const float (*A)[PP],
                                      const float (*B)[PP], int tid) {
    if (tid < 432) {
        int r  = tid % P;
        int c0 = (tid / P) * 3;
        float a0 = 0.f, a1 = 0.f, a2 = 0.f;
#pragma unroll
        for (int k = 0; k < P; k++) {
            float a = A[r][k];
            a0 += a * B[k][c0 + 0];
            a1 += a * B[k][c0 + 1];
            a2 += a * B[k][c0 + 2];
        }
        D[r][c0 + 0] = a0; D[r][c0 + 1] = a1; D[r][c0 + 2] = a2;
    }
    __syncthreads();
}

__device__ __forceinline__ void mm_nt(float (*D)[PP], const float (*A)[PP],
                                      const float (*B)[PP], int tid) {
    if (tid < 432) {
        int r  = tid % P;
        int c0 = (tid / P) * 3;
        float a0 = 0.f, a1 = 0.f, a2 = 0.f;
#pragma unroll
        for (int k = 0; k < P; k++) {
            float a = A[r][k];
            a0 += a * B[c0 + 0][k];
            a1 += a * B[c0 + 1][k];
            a2 += a * B[c0 + 2][k];
        }
        D[r][c0 + 0] = a0; D[r][c0 + 1] = a1; D[r][c0 + 2] = a2;
    }
    __syncthreads();
}

__device__ __forceinline__ void stage_w(float (*W)[PP], const float* __restrict__ w,
                                        const float* __restrict__ bias, int tid) {
    for (int i = tid; i < P * PP; i += NTB) {
        int r = i / PP, c = i % PP;
        float v = 0.f;
        if (r < CH && c < CH)       v = w[r * CH + c];
        else if (r < CH && c == CH) v = bias[r];
        else if (r == CH && c == CH) v = 1.f;
        W[r][c] = v;
    }
    __syncthreads();
}

// ---------------- Kernel GRAM: partial S, 8x4 blocks, i-paired accs ---------

#define GSTEP(t) do {                                                       \
    ulonglong2 a01 = *(const ulonglong2*)&Hs[t][8 * bi];                    \
    ulonglong2 a23 = *(const ulonglong2*)&Hs[t][8 * bi + 4];                \
    float4 bv4 = *(const float4*)&Hs[t][4 * bj];                            \
    ull b0 = pack2(bv4.x, bv4.x), b1 = pack2(bv4.y, bv4.y);                 \
    ull b2 = pack2(bv4.z, bv4.z), b3 = pack2(bv4.w, bv4.w);                 \
    fma2(acc[0],  a01.x, b0); fma2(acc[1],  a01.y, b0);                     \
    fma2(acc[2],  a23.x, b0); fma2(acc[3],  a23.y, b0);                     \
    fma2(acc[4],  a01.x, b1); fma2(acc[5],  a01.y, b1);                     \
    fma2(acc[6],  a23.x, b1); fma2(acc[7],  a23.y, b1);                     \
    fma2(acc[8],  a01.x, b2); fma2(acc[9],  a01.y, b2);                     \
    fma2(acc[10], a23.x, b2); fma2(acc[11], a23.y, b2);                     \
    fma2(acc[12], a01.x, b3); fma2(acc[13], a01.y, b3);                     \
    fma2(acc[14], a23.x, b3); fma2(acc[15], a23.y, b3);                     \
} while (0)

__global__ void __launch_bounds__(NTHREADS, 3) kernel_gram(const float* __restrict__ x)
{
    __shared__ float S[40][PP];                    // rows 36-39 = padding spill
    __shared__ __align__(16) float Hs[TT][GPITCH];

    int tid = threadIdx.x;
    int b   = blockIdx.x;
    int s   = blockIdx.y;

    for (int i = tid; i < 40 * PP; i += NTHREADS) (&S[0][0])[i] = 0.f;

    bool act = (tid < NGBLK * NPH);
    int bi = 0, bj = 0, sub = 0;
    if (act) {
        int blk = tid / NPH;
        sub = tid % NPH;
        int rem = blk;
        while (rem >= 9 - 2 * bi) { rem -= 9 - 2 * bi; bi++; }
        bj = 2 * bi + rem;       // 8-row block bi (i: 8bi..8bi+7), 4-col block bj
    }
    ull acc[16];
#pragma unroll
    for (int i = 0; i < 16; i++) acc[i] = 0ull;

    const float* xb = x + (size_t)b * 2 * TLEN * 17;
    int tbase = s * TSPLIT;

    for (int t0 = tbase; t0 < tbase + TSPLIT; t0 += TT) {
        __syncthreads();
        // coalesced float4 stage -> Hs[t][ch], ch = c*17+v
#pragma unroll
        for (int c = 0; c < 2; c++) {
            const float4* src = (const float4*)(xb + (size_t)c * TLEN * 17 + (size_t)t0 * 17);
            for (int j = tid; j < TT * 17 / 4; j += NTHREADS) {
                float4 v = src[j];
                int idx = 4 * j;
                int t = idx / 17, vv = idx - 17 * t;
                float comp[4] = {v.x, v.y, v.z, v.w};
#pragma unroll
                for (int e = 0; e < 4; e++) {
                    Hs[t][c * 17 + vv] = comp[e];
                    vv++; if (vv == 17) { vv = 0; t++; }
                }
            }
        }
        for (int i = tid; i < TT; i += NTHREADS) {
            Hs[i][34] = 1.f;
#pragma unroll
            for (int z = 35; z < 40; z++) Hs[i][z] = 0.f;
        }
        __syncthreads();

        if (act) {
#pragma unroll 2
            for (int t = sub; t < TT; t += NPH) GSTEP(t);
        }
    }
    __syncthreads();
    if (act) {
#pragma unroll
        for (int j = 0; j < 4; j++)
#pragma unroll
            for (int p = 0; p < 4; p++) {
                float lo, hi;
                unpack2(acc[j * 4 + p], lo, hi);
                atomicAdd(&S[8 * bi + 2 * p][4 * bj + j], lo);
                atomicAdd(&S[8 * bi + 2 * p + 1][4 * bj + j], hi);
            }
    }
    __syncthreads();
    // mirror: upper triangle (j >= i) is exact; overwrite the rest
    for (int i = tid; i < P * P; i += NTHREADS) {
        int r = i / P, c = i % P;
        if (r > c) S[r][c] = S[c][r];
    }
    __syncthreads();
    float* dst = g_part + (size_t)(b * NSPLIT + s) * P * P;
    for (int i = tid; i < P * P; i += NTHREADS) dst[i] = S[i / P][i % P];
}

// ---------------- Kernel B: attention-layer math per batch (512 thr) --------

__global__ void __launch_bounds__(NTB) kernel_b(
    const float* __restrict__ wq, const float* __restrict__ bq,
    const float* __restrict__ wk, const float* __restrict__ bk,
    const float* __restrict__ wv, const float* __restrict__ bv,
    const float* __restrict__ w1, const float* __restrict__ b1,
    const float* __restrict__ gamma, const float* __restrict__ beta,
    const float* __restrict__ mean, const float* __restrict__ var)
{
    __shared__ __align__(16) float smem[8][P][PP];
    float (*S)[PP]   = smem[0];
    float (*A)[PP]   = smem[1];
    float (*T1)[PP]  = smem[2];
    float (*G)[PP]   = smem[3];
    float (*M)[PP]   = smem[4];
    float (*W0)[PP]  = smem[5];
    float (*Wk_)[PP] = smem[6];
    float (*Wv_)[PP] = smem[7];

    int tid = threadIdx.x;
    int b   = blockIdx.x;

    // sum the 4 Gram partials
    const float* src = g_part + (size_t)b * NSPLIT * P * P;
    for (int i = tid; i < P * P; i += NTB) {
        float v = src[i] + src[P * P + i] + src[2 * P * P + i] + src[3 * P * P + i];
        S[i / P][i % P] = v;
    }
    __syncthreads();

    float scale = rsqrtf((float)TLEN);

    for (int layer = 0; layer < 3; layer++) {
        stage_w(W0,  wq + layer * CH * CH, bq + layer * CH, tid);
        stage_w(Wk_, wk + layer * CH * CH, bk + layer * CH, tid);
        stage_w(Wv_, wv + layer * CH * CH, bv + layer * CH, tid);

        mm_nn(T1, W0, S, tid);    // T1 = Wq' S
        mm_nt(G, T1, Wk_, tid);   // G  = Wq' S Wk'^T

        if (tid < CH) {
            float mx = -1e30f;
            for (int c = 0; c < CH; c++) mx = fmaxf(mx, G[tid][c] * scale);
            float sm = 0.f;
            for (int c = 0; c < CH; c++) {
                float e = expf(G[tid][c] * scale - mx);
                G[tid][c] = e; sm += e;
            }
            float inv = 1.f / sm;
            for (int c = 0; c < CH; c++) G[tid][c] *= inv;
            G[tid][34] = 0.f; G[tid][35] = 0.f;
        } else if (tid == CH) {
            for (int c = 0; c < PP; c++) { G[34][c] = 0.f; G[35][c] = 0.f; }
            G[34][34] = 1.f;
        }
        __syncthreads();

        mm_nn(M, G, Wv_, tid);    // M = attn' Wv''

        if (layer < 2) {          // S <- M S M^T
            mm_nn(T1, M, S, tid);
            mm_nt(S, T1, M, tid);
        }

        if (layer == 0) {
            for (int i = tid; i < P * PP; i += NTB) (&A[0][0])[i] = (&M[0][0])[i];
            __syncthreads();
        } else if (layer == 1) {
            mm_nn(T1, M, A, tid); // A <- M2 * M1
            for (int i = tid; i < P * PP; i += NTB) (&A[0][0])[i] = (&T1[0][0])[i];
            __syncthreads();
        } else {
            for (int i = tid; i < P * PP; i += NTB) {
                int r = i / PP, c = i % PP;
                float v = 0.f;
                if (r < 16) {
                    float iv = gamma[r] * rsqrtf(var[r] + 1e-5f);
                    if (c < CH)       v = iv * w1[r * CH + c];
                    else if (c == CH) v = iv * (b1[r] - mean[r]) + beta[r];
                }
                W0[r][c] = v;
            }
            __syncthreads();
            mm_nn(T1, W0, M, tid); // R   = W1h * M3
            mm_nn(G, T1, A, tid);  // W1f = R * (M2 M1)
            for (int i = tid; i < 16 * 35; i += NTB)
                g_W1f[b * 16 * 35 + i] = G[i / 35][i % 35];
        }
    }
}

// ---------------- Kernel C: pointwise head, direct global h reads -----------

__global__ void __launch_bounds__(CTT3) kernel_c(
    const float* __restrict__ x,
    const float* __restrict__ w2, const float* __restrict__ b2,
    float* __restrict__ out)
{
    __shared__ __align__(16) float Wt[35][16];   // transposed W1f: Wt[c][o]
    __shared__ float w2s[48];
    __shared__ float b2s[3];

    int tid = threadIdx.x;
    int b   = blockIdx.y;
    int t   = blockIdx.x * CTT3 + tid;

    for (int i = tid; i < 16 * 35; i += CTT3) {
        int c = i >> 4, o = i & 15;
        Wt[c][o] = g_W1f[b * 560 + o * 35 + c];
    }
    if (tid < 48) w2s[tid] = w2[tid];
    if (tid < 3)  b2s[tid] = b2[tid];
    __syncthreads();

    const float* p0 = x + ((size_t)(b * 2 + 0) * TLEN + t) * 17;
    const float* p1 = x + ((size_t)(b * 2 + 1) * TLEN + t) * 17;

    // init accumulators with the homogeneous bias row (16 floats = 8 ulls)
    ull u[8];
    {
        const ull* wb = (const ull*)&Wt[34][0];
#pragma unroll
        for (int p = 0; p < 8; p++) u[p] = wb[p];
    }

#pragma unroll
    for (int c = 0; c < 17; c++) {
        float hv = __ldg(p0 + c);
        ull hh = pack2(hv, hv);
        const ulonglong2* wr = (const ulonglong2*)&Wt[c][0];
        ulonglong2 wa = wr[0], wbv = wr[1], wc = wr[2], wd = wr[3];
        fma2(u[0], wa.x,  hh); fma2(u[1], wa.y,  hh);
        fma2(u[2], wbv.x, hh); fma2(u[3], wbv.y, hh);
        fma2(u[4], wc.x,  hh); fma2(u[5], wc.y,  hh);
        fma2(u[6], wd.x,  hh); fma2(u[7], wd.y,  hh);
    }
#pragma unroll
    for (int c = 0; c < 17; c++) {
        float hv = __ldg(p1 + c);
        ull hh = pack2(hv, hv);
        const ulonglong2* wr = (const ulonglong2*)&Wt[17 + c][0];
        ulonglong2 wa = wr[0], wbv = wr[1], wc = wr[2], wd = wr[3];
        fma2(u[0], wa.x,  hh); fma2(u[1], wa.y,  hh);
        fma2(u[2], wbv.x, hh); fma2(u[3], wbv.y, hh);
        fma2(u[4], wc.x,  hh); fma2(u[5], wc.y,  hh);
        fma2(u[6], wd.x,  hh); fma2(u[7], wd.y,  hh);
    }

    float f[16];
#pragma unroll
    for (int p = 0; p < 8; p++) unpack2(u[p], f[2 * p], f[2 * p + 1]);
#pragma unroll
    for (int o = 0; o < 16; o++) f[o] = (f[o] > 0.f) ? f[o] : 0.01f * f[o];

#pragma unroll
    for (int j = 0; j < 3; j++) {
        float sv = b2s[j];
#pragma unroll
        for (int o = 0; o < 16; o++) sv += w2s[j * 16 + o] * f[o];
        out[(size_t)(b * 3 + j) * TLEN + t] = sv;
    }
}

// ---------------------------------------------------------------------------

extern "C" void kernel_launch(void* const* d_in, const int* in_sizes, int n_in,
                              void* d_out, int out_size) {
    const float* x     = (const float*)d_in[0];
    const float* wq    = (const float*)d_in[1];
    const float* bq    = (const float*)d_in[2];
    const float* wk    = (const float*)d_in[3];
    const float* bk    = (const float*)d_in[4];
    const float* wv    = (const float*)d_in[5];
    const float* bv    = (const float*)d_in[6];
    const float* w1    = (const float*)d_in[7];
    const float* b1    = (const float*)d_in[8];
    const float* gamma = (const float*)d_in[9];
    const float* beta  = (const float*)d_in[10];
    const float* mean  = (const float*)d_in[11];
    const float* var   = (const float*)d_in[12];
    const float* w2    = (const float*)d_in[13];
    const float* b2    = (const float*)d_in[14];
    float* out = (float*)d_out;

    dim3 gg(BATCH, NSPLIT);
    kernel_gram<<<gg, NTHREADS>>>(x);
    kernel_b<<<BATCH, NTB>>>(wq, bq, wk, bk, wv, bv,
                             w1, b1, gamma, beta, mean, var);
    dim3 gc(TLEN / CTT3, BATCH);
    kernel_c<<<gc, CTT3>>>(x, w2, b2, out);
}

// round 16
// speedup vs baseline: 1.3109x; 1.3109x over previous
#include <cuda_runtime.h>
#include <cuda_fp16.h>
#include <cstdint>

#define BATCH    512
#define TLEN     2048
#define CH       34
#define P        36
#define PP       37
#define P48      48
#define GP72     72            // fp16 pitch (elements)
#define PB       144           // bytes per row (16B-aligned, conflict-free for ldmatrix)
#define NSPLIT   2
#define KSPLIT   (TLEN / NSPLIT)
#define KCH      64            // t per staged chunk
#define NCHUNK   (KSPLIT / KCH)
#define NGT      256           // gram threads (8 warps)
#define NJOBS    15
#define NTB      512
#define CTT3     128

typedef unsigned long long ull;

__device__ float g_W1f[BATCH * 16 * 35];
__device__ float g_part[BATCH * NSPLIT * P * P];

// ---------------- helpers ---------------------------------------------------

__device__ __forceinline__ uint32_t smem_u32(const void* p) {
    uint32_t a;
    asm("{ .reg .u64 t; cvta.to.shared.u64 t, %1; cvt.u32.u64 %0, t; }" : "=r"(a) : "l"(p));
    return a;
}
__device__ __forceinline__ void sts16(uint32_t addr, unsigned short v) {
    asm volatile("st.shared.b16 [%0], %1;" :: "r"(addr), "h"(v));
}
__device__ __forceinline__ ull pack2(float lo, float hi) {
    ull r; asm("mov.b64 %0, {%1, %2};" : "=l"(r) : "f"(lo), "f"(hi)); return r;
}
__device__ __forceinline__ void unpack2(ull v, float& lo, float& hi) {
    asm("mov.b64 {%0, %1}, %2;" : "=f"(lo), "=f"(hi) : "l"(v));
}
__device__ __forceinline__ void fma2(ull& d, ull a, ull b) {
    asm("fma.rn.f32x2 %0, %1, %2, %0;" : "+l"(d) : "l"(a), "l"(b));
}
__device__ __forceinline__ void ldsm4(uint32_t& r0, uint32_t& r1, uint32_t& r2,
                                      uint32_t& r3, uint32_t a) {
    asm volatile("ldmatrix.sync.aligned.m8n8.x4.shared.b16 {%0,%1,%2,%3}, [%4];"
                 : "=r"(r0), "=r"(r1), "=r"(r2), "=r"(r3) : "r"(a));
}
__device__ __forceinline__ void mma16816(float* c, uint32_t a0, uint32_t a1,
                                         uint32_t a2, uint32_t a3,
                                         uint32_t b0, uint32_t b1) {
    asm volatile(
        "mma.sync.aligned.m16n8k16.row.col.f32.f16.f16.f32 "
        "{%0,%1,%2,%3}, {%4,%5,%6,%7}, {%8,%9}, {%0,%1,%2,%3};"
        : "+f"(c[0]), "+f"(c[1]), "+f"(c[2]), "+f"(c[3])
        : "r"(a0), "r"(a1), "r"(a2), "r"(a3), "r"(b0), "r"(b1));
}

// ---------------- Kernel GRAM (warp HMMA, fp16 2-term split) ----------------
// Per (b, s): S = H H^T over K = 1024 t.  H rows = 48 channels (34 real + 1s + pad).
// x = hi + lo, both fp16.  D1 = hi hi^T (upper 6 tiles), D2 = hi lo^T (9 tiles).
// S = D1 + D2 + D2^T  (lo*lo^T dropped: ~2^-22 relative).

__global__ void __launch_bounds__(NGT) kernel_gram_mma(const float* __restrict__ x)
{
    __shared__ __align__(16) __half HiS[P48 * GP72];
    __shared__ __align__(16) __half LoS[P48 * GP72];
    __shared__ float D1s[P48][49];
    __shared__ float D2s[P48][49];

    int tid  = threadIdx.x;
    int lane = tid & 31, wid = tid >> 5;
    int b = blockIdx.x, s = blockIdx.y;

    uint32_t hiA = smem_u32(HiS), loA = smem_u32(LoS);

    // zero hi + lo buffers (rows 35-47 / pad cols stay zero forever)
    {
        uint4 z = make_uint4(0, 0, 0, 0);
        uint4* ph = (uint4*)HiS; uint4* pl = (uint4*)LoS;
        for (int i = tid; i < P48 * GP72 * 2 / 16; i += NGT) { ph[i] = z; pl[i] = z; }
    }
    __syncthreads();   // RACE FIX: zeroing must complete before row-34 ones land
    // homogeneous row 34 of hi = 1.0 fp16 (constant across chunks)
    if (tid < KCH) sts16(hiA + 34 * PB + 2 * tid, (unsigned short)0x3C00);

    // job table: (op, ti, tj).  op0: D1 = hi*hi^T, op1: D2 = hi*lo^T
    const int JOP[NJOBS] = {0,0,0,0,0,0, 1,1,1,1,1,1,1,1,1};
    const int JTI[NJOBS] = {0,0,0,1,1,2, 0,0,0,1,1,1,2,2,2};
    const int JTJ[NJOBS] = {0,1,2,1,2,2, 0,1,2,0,1,2,0,1,2};

    int nj = (wid + 8 < NJOBS) ? 2 : 1;
    int jid[2] = {wid, wid + 8 < NJOBS ? wid + 8 : wid};
    uint32_t aBase[2], bBase[2];
#pragma unroll
    for (int j = 0; j < 2; j++) {
        int ti = JTI[jid[j]], tj = JTJ[jid[j]];
        uint32_t bbuf = JOP[jid[j]] ? loA : hiA;
        aBase[j] = hiA + (uint32_t)(ti * 16 + (lane & 15)) * PB + ((lane >> 4) << 4);
        int brow = tj * 16 + (lane & 7) + ((lane >> 4) << 3);
        bBase[j] = bbuf + (uint32_t)brow * PB + (((lane >> 3) & 1) << 4);
    }
    float acc[2][8];
#pragma unroll
    for (int j = 0; j < 2; j++)
#pragma unroll
        for (int i = 0; i < 8; i++) acc[j][i] = 0.f;

    const float* xb = x + (size_t)b * 2 * TLEN * 17;

    for (int ci = 0; ci < NCHUNK; ci++) {
        __syncthreads();
        int t0 = s * KSPLIT + ci * KCH;
        // stage rows 0-33: coalesced float4 reads -> fp16 hi/lo at [ch][t]
#pragma unroll
        for (int c = 0; c < 2; c++) {
            const float4* src = (const float4*)(xb + (size_t)c * TLEN * 17 + (size_t)t0 * 17);
            for (int j = tid; j < KCH * 17 / 4; j += NGT) {
                float4 v = src[j];
                int idx = 4 * j;
                int t = idx / 17, vv = idx - 17 * t;
                float comp[4] = {v.x, v.y, v.z, v.w};
#pragma unroll
                for (int e = 0; e < 4; e++) {
                    uint32_t off = (uint32_t)(c * 17 + vv) * PB + 2 * t;
                    __half h = __float2half_rn(comp[e]);
                    float hf = __half2float(h);
                    __half l = __float2half_rn(comp[e] - hf);
                    sts16(hiA + off, __half_as_ushort(h));
                    sts16(loA + off, __half_as_ushort(l));
                    vv++; if (vv == 17) { vv = 0; t++; }
                }
            }
        }
        __syncthreads();

#pragma unroll
        for (int ks = 0; ks < 4; ks++) {
#pragma unroll
            for (int j = 0; j < 2; j++) {
                if (j < nj) {
                    uint32_t a0, a1, a2, a3, b0, b1, b2, b3;
                    ldsm4(a0, a1, a2, a3, aBase[j] + ks * 32);
                    ldsm4(b0, b1, b2, b3, bBase[j] + ks * 32);
                    mma16816(acc[j],     a0, a1, a2, a3, b0, b1);
                    mma16816(acc[j] + 4, a0, a1, a2, a3, b2, b3);
                }
            }
        }
    }

    // store fragments (disjoint tiles -> no races)
#pragma unroll
    for (int j = 0; j < 2; j++) {
        if (j < nj) {
            int op = JOP[jid[j]], ti = JTI[jid[j]], tj = JTJ[jid[j]];
            float (*T)[49] = op ? D2s : D1s;
            int r0 = ti * 16 + (lane >> 2);
            int c0 = tj * 16 + 2 * (lane & 3);
            T[r0][c0]         = acc[j][0]; T[r0][c0 + 1]     = acc[j][1];
            T[r0 + 8][c0]     = acc[j][2]; T[r0 + 8][c0 + 1] = acc[j][3];
            T[r0][c0 + 8]     = acc[j][4]; T[r0][c0 + 9]     = acc[j][5];
            T[r0 + 8][c0 + 8] = acc[j][6]; T[r0 + 8][c0 + 9] = acc[j][7];
        }
    }
    __syncthreads();

    // combine S = D1(sym) + D2 + D2^T, write partial
    float* dst = g_part + (size_t)(b * NSPLIT + s) * P * P;
    for (int i = tid; i < P * P; i += NGT) {
        int r = i / P, c = i % P;
        int rm = r < c ? r : c, cm = r < c ? c : r;
        dst[i] = D1s[rm][cm] + D2s[r][c] + D2s[c][r];
    }
}

// ---------------- 36x36 shared-memory matmuls (432 active threads) ----------

__device__ __forceinline__ void mm_nn(float (*D)[PP], const float (*A)[PP],
                                      const float (*B)[PP], int tid) {
    if (tid < 432) {
        int r = tid % P, c0 = (tid / P) * 3;
        float a0 = 0.f, a1 = 0.f, a2 = 0.f;
#pragma unroll
        for (int k = 0; k < P; k++) {
            float a = A[r][k];
            a0 += a * B[k][c0 + 0]; a1 += a * B[k][c0 + 1]; a2 += a * B[k][c0 + 2];
        }
        D[r][c0] = a0; D[r][c0 + 1] = a1; D[r][c0 + 2] = a2;
    }
    __syncthreads();
}
__device__ __forceinline__ void mm_nt(float (*D)[PP], const float (*A)[PP],
                                      const float (*B)[PP], int tid) {
    if (tid < 432) {
        int r = tid % P, c0 = (tid / P) * 3;
        float a0 = 0.f, a1 = 0.f, a2 = 0.f;
#pragma unroll
        for (int k = 0; k < P; k++) {
            float a = A[r][k];
            a0 += a * B[c0 + 0][k]; a1 += a * B[c0 + 1][k]; a2 += a * B[c0 + 2][k];
        }
        D[r][c0] = a0; D[r][c0 + 1] = a1; D[r][c0 + 2] = a2;
    }
    __syncthreads();
}
__device__ __forceinline__ void stage_w(float (*W)[PP], const float* __restrict__ w,
                                        const float* __restrict__ bias, int tid) {
    for (int i = tid; i < P * PP; i += NTB) {
        int r = i / PP, c = i % PP;
        float v = 0.f;
        if (r < CH && c < CH)        v = w[r * CH + c];
        else if (r < CH && c == CH)  v = bias[r];
        else if (r == CH && c == CH) v = 1.f;
        W[r][c] = v;
    }
    __syncthreads();
}

// ---------------- Kernel B: attention-layer math per batch ------------------

__global__ void __launch_bounds__(NTB) kernel_b(
    const float* __restrict__ wq, const float* __restrict__ bq,
    const float* __restrict__ wk, const float* __restrict__ bk,
    const float* __restrict__ wv, const float* __restrict__ bv,
    const float* __restrict__ w1, const float* __restrict__ b1,
    const float* __restrict__ gamma, const float* __restrict__ beta,
    const float* __restrict__ mean, const float* __restrict__ var)
{
    __shared__ __align__(16) float smem[8][P][PP];
    float (*S)[PP] = smem[0]; float (*A)[PP] = smem[1];
    float (*T1)[PP] = smem[2]; float (*G)[PP] = smem[3];
    float (*M)[PP] = smem[4]; float (*W0)[PP] = smem[5];
    float (*Wk_)[PP] = smem[6]; float (*Wv_)[PP] = smem[7];

    int tid = threadIdx.x, b = blockIdx.x;

    const float* src = g_part + (size_t)b * NSPLIT * P * P;
    for (int i = tid; i < P * P; i += NTB)
        S[i / P][i % P] = src[i] + src[P * P + i];
    __syncthreads();

    float scale = rsqrtf((float)TLEN);

    for (int layer = 0; layer < 3; layer++) {
        stage_w(W0,  wq + layer * CH * CH, bq + layer * CH, tid);
        stage_w(Wk_, wk + layer * CH * CH, bk + layer * CH, tid);
        stage_w(Wv_, wv + layer * CH * CH, bv + layer * CH, tid);

        mm_nn(T1, W0, S, tid);
        mm_nt(G, T1, Wk_, tid);

        if (tid < CH) {
            float mx = -1e30f;
            for (int c = 0; c < CH; c++) mx = fmaxf(mx, G[tid][c] * scale);
            float sm = 0.f;
            for (int c = 0; c < CH; c++) {
                float e = expf(G[tid][c] * scale - mx);
                G[tid][c] = e; sm += e;
            }
            float inv = 1.f / sm;
            for (int c = 0; c < CH; c++) G[tid][c] *= inv;
            G[tid][34] = 0.f; G[tid][35] = 0.f;
        } else if (tid == CH) {
            for (int c = 0; c < PP; c++) { G[34][c] = 0.f; G[35][c] = 0.f; }
            G[34][34] = 1.f;
        }
        __syncthreads();

        mm_nn(M, G, Wv_, tid);

        if (layer < 2) { mm_nn(T1, M, S, tid); mm_nt(S, T1, M, tid); }

        if (layer == 0) {
            for (int i = tid; i < P * PP; i += NTB) (&A[0][0])[i] = (&M[0][0])[i];
            __syncthreads();
        } else if (layer == 1) {
            mm_nn(T1, M, A, tid);
            for (int i = tid; i < P * PP; i += NTB) (&A[0][0])[i] = (&T1[0][0])[i];
            __syncthreads();
        } else {
            for (int i = tid; i < P * PP; i += NTB) {
                int r = i / PP, c = i % PP;
                float v = 0.f;
                if (r < 16) {
                    float iv = gamma[r] * rsqrtf(var[r] + 1e-5f);
                    if (c < CH)       v = iv * w1[r * CH + c];
                    else if (c == CH) v = iv * (b1[r] - mean[r]) + beta[r];
                }
                W0[r][c] = v;
            }
            __syncthreads();
            mm_nn(T1, W0, M, tid);
            mm_nn(G, T1, A, tid);
            for (int i = tid; i < 16 * 35; i += NTB)
                g_W1f[b * 16 * 35 + i] = G[i / 35][i % 35];
        }
    }
}

// ---------------- Kernel C: pointwise head (staged, 1 t per thread) ---------

__global__ void __launch_bounds__(CTT3) kernel_c(
    const float* __restrict__ x,
    const float* __restrict__ w2, const float* __restrict__ b2,
    float* __restrict__ out)
{
    __shared__ float Hs[CTT3][35];
    __shared__ __align__(16) float Wt[35][16];
    __shared__ float w2s[48];
    __shared__ float b2s[3];

    int tid = threadIdx.x;
    int b = blockIdx.y, t0 = blockIdx.x * CTT3;

    for (int i = tid; i < 16 * 35; i += CTT3) {
        int c = i >> 4, o = i & 15;
        Wt[c][o] = g_W1f[b * 560 + o * 35 + c];
    }
    if (tid < 48) w2s[tid] = w2[tid];
    if (tid < 3)  b2s[tid] = b2[tid];

#pragma unroll
    for (int c = 0; c < 2; c++) {
        const float4* src = (const float4*)(x + ((size_t)(b * 2 + c) * TLEN + t0) * 17);
        for (int j = tid; j < CTT3 * 17 / 4; j += CTT3) {
            float4 v = src[j];
            int idx = 4 * j;
            int t = idx / 17, vv = idx - 17 * t;
            float comp[4] = {v.x, v.y, v.z, v.w};
#pragma unroll
            for (int e = 0; e < 4; e++) {
                Hs[t][c * 17 + vv] = comp[e];
                vv++; if (vv == 17) { vv = 0; t++; }
            }
        }
    }
    __syncthreads();

    ull u[8];
    {
        const ull* wb = (const ull*)&Wt[34][0];
#pragma unroll
        for (int p = 0; p < 8; p++) u[p] = wb[p];
    }
#pragma unroll
    for (int c = 0; c < CH; c++) {
        float hv = Hs[tid][c];
        ull hh = pack2(hv, hv);
        const ulonglong2* wr = (const ulonglong2*)&Wt[c][0];
        ulonglong2 wa = wr[0], wbv = wr[1];
        fma2(u[0], wa.x,  hh); fma2(u[1], wa.y,  hh);
        fma2(u[2], wbv.x, hh); fma2(u[3], wbv.y, hh);
    }
#pragma unroll
    for (int c = 0; c < CH; c++) {
        float hv = Hs[tid][c];
        ull hh = pack2(hv, hv);
        const ulonglong2* wr = (const ulonglong2*)&Wt[c][8];
        ulonglong2 wc = wr[0], wd = wr[1];
        fma2(u[4], wc.x, hh); fma2(u[5], wc.y, hh);
        fma2(u[6], wd.x, hh); fma2(u[7], wd.y, hh);
    }

    float f[16];
#pragma unroll
    for (int p = 0; p < 8; p++) unpack2(u[p], f[2 * p], f[2 * p + 1]);
#pragma unroll
    for (int o = 0; o < 16; o++) f[o] = (f[o] > 0.f) ? f[o] : 0.01f * f[o];

#pragma unroll
    for (int j = 0; j < 3; j++) {
        float sv = b2s[j];
#pragma unroll
        for (int o = 0; o < 16; o++) sv += w2s[j * 16 + o] * f[o];
        out[(size_t)(b * 3 + j) * TLEN + t0 + tid] = sv;
    }
}

// ---------------------------------------------------------------------------

extern "C" void kernel_launch(void* const* d_in, const int* in_sizes, int n_in,
                              void* d_out, int out_size) {
    const float* x     = (const float*)d_in[0];
    const float* wq    = (const float*)d_in[1];
    const float* bq    = (const float*)d_in[2];
    const float* wk    = (const float*)d_in[3];
    const float* bk    = (const float*)d_in[4];
    const float* wv    = (const float*)d_in[5];
    const float* bv    = (const float*)d_in[6];
    const float* w1    = (const float*)d_in[7];
    const float* b1    = (const float*)d_in[8];
    const float* gamma = (const float*)d_in[9];
    const float* beta  = (const float*)d_in[10];
    const float* mean  = (const float*)d_in[11];
    const float* var   = (const float*)d_in[12];
    const float* w2    = (const float*)d_in[13];
    const float* b2    = (const float*)d_in[14];
    float* out = (float*)d_out;

    dim3 gg(BATCH, NSPLIT);
    kernel_gram_mma<<<gg, NGT>>>(x);
    kernel_b<<<BATCH, NTB>>>(wq, bq, wk, bk, wv, bv,
                             w1, b1, gamma, beta, mean, var);
    dim3 gc(TLEN / CTT3, BATCH);
    kernel_c<<<gc, CTT3>>>(x, w2, b2, out);
}